// round 13
// baseline (speedup 1.0000x reference)
#include <cuda_runtime.h>
#include <stdint.h>

#define EMB 64
#define HIST 50
#define ROW_F4 (HIST * EMB / 4)   // 800 float4 per output row
#define ENT_F4 (EMB / 4)          // 16 float4 per embedding entry
#define NTHREADS 160              // 800 / 160 = exactly 5 float4 per thread

// ---- L2 eviction-priority accessors (sm_80+ PTX cache hints) ----
// evict_last: pin embeddings resident in L2 across graph replays.
// evict_first: stream stores through a small L2 pool without evicting them.

__device__ __forceinline__ float4 ldg_resident(const float4* __restrict__ p) {
    float4 v;
    asm volatile(
        "{\n\t"
        ".reg .b64 pol;\n\t"
        "createpolicy.fractional.L2::evict_last.b64 pol, 1.0;\n\t"
        "ld.global.nc.L2::cache_hint.v4.f32 {%0,%1,%2,%3}, [%4], pol;\n\t"
        "}"
        : "=f"(v.x), "=f"(v.y), "=f"(v.z), "=f"(v.w)
        : "l"(p));
    return v;
}

__device__ __forceinline__ void stg_stream(float4* __restrict__ p, float4 v) {
    asm volatile(
        "{\n\t"
        ".reg .b64 pol;\n\t"
        "createpolicy.fractional.L2::evict_first.b64 pol, 1.0;\n\t"
        "st.global.L2::cache_hint.v4.f32 [%0], {%1,%2,%3,%4}, pol;\n\t"
        "}"
        :: "l"(p), "f"(v.x), "f"(v.y), "f"(v.z), "f"(v.w)
        : "memory");
}

// lower_bound(pos, n, key) with guessed fast path.
__device__ __forceinline__ int lower_bound_guess(
    const int* __restrict__ p, int n, int key, long long num, int den)
{
    int g = (int)(num / den);
    if (g < 0) g = 0;
    if (g > n) g = n;

    int pg   = (g < n) ? __ldg(&p[g])     : 0x7fffffff;
    int pgm1 = (g > 0) ? __ldg(&p[g - 1]) : 0;
    if (g == 0) pgm1 = key - 1;                 // always "< key"
    if (pg >= key && pgm1 < key) return g;      // guess exact

    int lo, hi;
    if (pg < key) {
        int prev = g, step = 1, cur = g + 1;
        while (cur < n && __ldg(&p[cur]) < key) {
            prev = cur; step <<= 1; cur = prev + step;
        }
        lo = prev + 1;
        hi = (cur < n) ? cur : n;
    } else {
        hi = g;
        int step = 1, cur = g - 1;
        while (cur >= 0 && __ldg(&p[cur]) >= key) {
            hi = cur; step <<= 1; cur = g - step;
        }
        lo = (cur < 0) ? 0 : cur + 1;
    }
    while (lo < hi) {
        int mid = (lo + hi) >> 1;
        if (__ldg(&p[mid]) < key) lo = mid + 1; else hi = mid;
    }
    return lo;
}

__global__ void __launch_bounds__(NTHREADS) remap_fused_kernel(
    const float4* __restrict__ emb,
    const int*    __restrict__ pos,
    int n_valid, int batch,
    float4* __restrict__ out)
{
    __shared__ int s_bound[2];

    const int b   = blockIdx.x;
    const int tid = threadIdx.x;

    // Boundary searches in SEPARATE warps so the two paths run concurrently.
    if (tid == 0) {
        s_bound[0] = lower_bound_guess(pos, n_valid, b,
                                       (long long)b * n_valid, batch);
    } else if (tid == 32) {
        const int key = b + 1;
        s_bound[1] = lower_bound_guess(pos, n_valid, key,
                                       (long long)key * n_valid, batch);
    }
    __syncthreads();

    const int start = s_bound[0];
    int cnt_f4 = (s_bound[1] - start) * ENT_F4;
    if (cnt_f4 > ROW_F4) cnt_f4 = ROW_F4;       // mode="drop" clamp

    float4* __restrict__ orow = out + (size_t)b * ROW_F4;
    const float4* __restrict__ irow = emb + (size_t)start * ENT_F4;
    const float4 zero = make_float4(0.f, 0.f, 0.f, 0.f);

    // exactly 5 float4 per thread
    const int v0 = tid;
    const int v1 = tid + 1 * NTHREADS;
    const int v2 = tid + 2 * NTHREADS;
    const int v3 = tid + 3 * NTHREADS;
    const int v4 = tid + 4 * NTHREADS;

    // front-batch 5 independent loads (MLP=5), then 5 stores
    float4 a0 = (v0 < cnt_f4) ? ldg_resident(&irow[v0]) : zero;
    float4 a1 = (v1 < cnt_f4) ? ldg_resident(&irow[v1]) : zero;
    float4 a2 = (v2 < cnt_f4) ? ldg_resident(&irow[v2]) : zero;
    float4 a3 = (v3 < cnt_f4) ? ldg_resident(&irow[v3]) : zero;
    float4 a4 = (v4 < cnt_f4) ? ldg_resident(&irow[v4]) : zero;

    stg_stream(&orow[v0], a0);
    stg_stream(&orow[v1], a1);
    stg_stream(&orow[v2], a2);
    stg_stream(&orow[v3], a3);
    stg_stream(&orow[v4], a4);
}

extern "C" void kernel_launch(void* const* d_in, const int* in_sizes, int n_in,
                              void* d_out, int out_size)
{
    const float4* emb = (const float4*)d_in[0];
    const int*    pos = (const int*)d_in[1];
    const int n_valid = in_sizes[1];
    const int batch   = out_size / (HIST * EMB);

    remap_fused_kernel<<<batch, NTHREADS>>>(emb, pos, n_valid, batch,
                                            (float4*)d_out);
}

// round 17
// speedup vs baseline: 1.1245x; 1.1245x over previous
#include <cuda_runtime.h>
#include <stdint.h>

#define EMB 64
#define HIST 50
#define ROW_F4 (HIST * EMB / 4)   // 800 float4 per output row
#define ENT_F4 (EMB / 4)          // 16 float4 per embedding entry
#define NTHREADS 160              // 800 / 160 = exactly 5 float4 per thread

// lower_bound(pos, n, key) with guessed fast path.
// Fast path: two INDEPENDENT loads verify the guess in one L2 round-trip.
// Fallback: gallop + binary (arbitrary sorted input stays correct).
__device__ __forceinline__ int lower_bound_guess(
    const int* __restrict__ p, int n, int key, long long num, int den)
{
    int g = (int)(num / den);
    if (g < 0) g = 0;
    if (g > n) g = n;

    int pg   = (g < n) ? __ldg(&p[g])     : 0x7fffffff;
    int pgm1 = (g > 0) ? __ldg(&p[g - 1]) : 0;
    if (g == 0) pgm1 = key - 1;                 // always "< key"
    if (pg >= key && pgm1 < key) return g;      // guess exact

    int lo, hi;
    if (pg < key) {
        int prev = g, step = 1, cur = g + 1;
        while (cur < n && __ldg(&p[cur]) < key) {
            prev = cur; step <<= 1; cur = prev + step;
        }
        lo = prev + 1;
        hi = (cur < n) ? cur : n;
    } else {
        hi = g;
        int step = 1, cur = g - 1;
        while (cur >= 0 && __ldg(&p[cur]) >= key) {
            hi = cur; step <<= 1; cur = g - step;
        }
        lo = (cur < 0) ? 0 : cur + 1;
    }
    while (lo < hi) {
        int mid = (lo + hi) >> 1;
        if (__ldg(&p[mid]) < key) lo = mid + 1; else hi = mid;
    }
    return lo;
}

__global__ void __launch_bounds__(NTHREADS) remap_fused_kernel(
    const float4* __restrict__ emb,
    const int*    __restrict__ pos,
    int n_valid, int batch,
    float4* __restrict__ out)
{
    __shared__ int s_bound[2];

    const int b   = blockIdx.x;
    const int tid = threadIdx.x;

    // Boundary searches in SEPARATE warps so the two paths run concurrently.
    if (tid == 0) {
        s_bound[0] = lower_bound_guess(pos, n_valid, b,
                                       (long long)b * n_valid, batch);
    } else if (tid == 32) {
        const int key = b + 1;
        s_bound[1] = lower_bound_guess(pos, n_valid, key,
                                       (long long)key * n_valid, batch);
    }
    __syncthreads();

    const int start = s_bound[0];
    int cnt_f4 = (s_bound[1] - start) * ENT_F4;
    if (cnt_f4 > ROW_F4) cnt_f4 = ROW_F4;       // mode="drop" clamp

    float4* __restrict__ orow = out + (size_t)b * ROW_F4;
    const float4* __restrict__ irow = emb + (size_t)start * ENT_F4;
    const float4 zero = make_float4(0.f, 0.f, 0.f, 0.f);

    // exactly 5 float4 per thread, no bounds predication on the row
    const int v0 = tid;
    const int v1 = tid + 1 * NTHREADS;
    const int v2 = tid + 2 * NTHREADS;
    const int v3 = tid + 3 * NTHREADS;
    const int v4 = tid + 4 * NTHREADS;

    // Loads: default policy — let the ~105MB input occupy L2 naturally.
    // Stores: write-through (STG.WT) — push the 210MB write stream toward
    // DRAM without promoting written lines in L2, preserving read residency.
    float4 a0 = (v0 < cnt_f4) ? __ldg(&irow[v0]) : zero;
    float4 a1 = (v1 < cnt_f4) ? __ldg(&irow[v1]) : zero;
    float4 a2 = (v2 < cnt_f4) ? __ldg(&irow[v2]) : zero;
    float4 a3 = (v3 < cnt_f4) ? __ldg(&irow[v3]) : zero;
    float4 a4 = (v4 < cnt_f4) ? __ldg(&irow[v4]) : zero;

    __stwt(&orow[v0], a0);
    __stwt(&orow[v1], a1);
    __stwt(&orow[v2], a2);
    __stwt(&orow[v3], a3);
    __stwt(&orow[v4], a4);
}

extern "C" void kernel_launch(void* const* d_in, const int* in_sizes, int n_in,
                              void* d_out, int out_size)
{
    const float4* emb = (const float4*)d_in[0];
    const int*    pos = (const int*)d_in[1];
    const int n_valid = in_sizes[1];
    const int batch   = out_size / (HIST * EMB);

    remap_fused_kernel<<<batch, NTHREADS>>>(emb, pos, n_valid, batch,
                                            (float4*)d_out);
}